// round 13
// baseline (speedup 1.0000x reference)
#include <cuda_runtime.h>
#include <cuda_bf16.h>
#include <cstdint>
#include <cstddef>

#define Hdim 1024
#define Bdim 8
#define Tdim 2048
#define G3   3072
#define NCTA 128

typedef unsigned long long ull;

// ---------------- device-global scratch (no runtime allocation) -------------
__device__ __align__(256) float    g_xproj[(size_t)Bdim * Tdim * G3];  // [b][t][3H]
__device__ __align__(256) float    g_hbuf[2][Hdim * Bdim];             // [unit][b]
__device__ __align__(256) unsigned g_flags[NCTA * 64];                 // 256B stride/CTA
__device__ __align__(256) unsigned g_epoch[64];                        // broadcast word

// ---------------- packed fp32x2 helpers ------------------------------------
__device__ __forceinline__ ull ffma2(ull a, ull b, ull c) {
    ull d;
    asm("fma.rn.f32x2 %0, %1, %2, %3;" : "=l"(d) : "l"(a), "l"(b), "l"(c));
    return d;
}
__device__ __forceinline__ ull pack2(float x, float y) {
    ull d; asm("mov.b64 %0, {%1, %2};" : "=l"(d) : "f"(x), "f"(y)); return d;
}
__device__ __forceinline__ void unpack2(ull d, float& x, float& y) {
    asm("mov.b64 {%0, %1}, %2;" : "=f"(x), "=f"(y) : "l"(d));
}

// ============================================================================
// Phase 1 (verbatim R2): x_proj = x @ W_ih^T + b_ih. 128x128 tile, BK=16.
// ============================================================================
#define PA 132

__global__ void __launch_bounds__(256)
xproj_kernel(const float* __restrict__ A, const float* __restrict__ W,
             const float* __restrict__ bias)
{
    __shared__ float As[16][PA];
    __shared__ float Bs[16][PA];

    const int tid = threadIdx.x;
    const int tx  = tid & 15;
    const int ty  = tid >> 4;
    const int m0  = blockIdx.y * 128;
    const int n0  = blockIdx.x * 128;

    const float* Abase = &A[(size_t)m0 * Hdim];
    const float* Wbase = &W[(size_t)n0 * Hdim];

    ull acc[8][4];
    #pragma unroll
    for (int i = 0; i < 8; i++)
        #pragma unroll
        for (int j = 0; j < 4; j++) acc[i][j] = 0ULL;

    for (int kt = 0; kt < Hdim / 16; kt++) {
        const int k0 = kt * 16;
        #pragma unroll
        for (int L = 0; L < 2; L++) {
            int id = tid + L * 256;
            int m  = id >> 2;
            int k4 = (id & 3) << 2;
            float4 va = *(const float4*)&Abase[(size_t)m * Hdim + k0 + k4];
            As[k4 + 0][m] = va.x; As[k4 + 1][m] = va.y;
            As[k4 + 2][m] = va.z; As[k4 + 3][m] = va.w;
            float4 vb = *(const float4*)&Wbase[(size_t)m * Hdim + k0 + k4];
            Bs[k4 + 0][m] = vb.x; Bs[k4 + 1][m] = vb.y;
            Bs[k4 + 2][m] = vb.z; Bs[k4 + 3][m] = vb.w;
        }
        __syncthreads();

        #pragma unroll
        for (int kk = 0; kk < 16; kk++) {
            float4 a0 = *(const float4*)&As[kk][ty * 8];
            float4 a1 = *(const float4*)&As[kk][ty * 8 + 4];
            ull a2[8] = { pack2(a0.x, a0.x), pack2(a0.y, a0.y),
                          pack2(a0.z, a0.z), pack2(a0.w, a0.w),
                          pack2(a1.x, a1.x), pack2(a1.y, a1.y),
                          pack2(a1.z, a1.z), pack2(a1.w, a1.w) };
            ulonglong2 b01 = *(const ulonglong2*)&Bs[kk][tx * 8];
            ulonglong2 b23 = *(const ulonglong2*)&Bs[kk][tx * 8 + 4];
            ull bp[4] = { b01.x, b01.y, b23.x, b23.y };
            #pragma unroll
            for (int i = 0; i < 8; i++)
                #pragma unroll
                for (int j = 0; j < 4; j++)
                    acc[i][j] = ffma2(a2[i], bp[j], acc[i][j]);
        }
        __syncthreads();
    }

    float bb[8];
    #pragma unroll
    for (int j = 0; j < 8; j++) bb[j] = bias[n0 + tx * 8 + j];

    #pragma unroll
    for (int i = 0; i < 8; i++) {
        size_t row = (size_t)(m0 + ty * 8 + i);
        float* crow = &g_xproj[row * G3 + n0 + tx * 8];
        #pragma unroll
        for (int j = 0; j < 4; j++) {
            float lo, hi; unpack2(acc[i][j], lo, hi);
            float2 v; v.x = lo + bb[2 * j]; v.y = hi + bb[2 * j + 1];
            *(float2*)(crow + 2 * j) = v;
        }
    }
}

// ============================================================================
// Phase 2: R2-verbatim pipeline; ONLY the grid barrier is replaced by a
// two-hop broadcast barrier:
//   arrive:   tid0 st.release.gpu -> own flag (parallel, no serialization)
//   aggregate: CTA0 warp0 polls all 128 flags (acquire), lane0 publishes epoch
//   wait:     every CTA's tid0 polls the single epoch line, syncthreads relay
// Ordering: flagX(rel) -> agg(acq) -> epoch(rel) -> ctaY(acq) is transitive.
// Bases are read from owner-only words: race-free and graph-replay-safe.
// ============================================================================
#define WPITCH 1025
#define OFF_W    0
#define OFF_H    (24 * WPITCH)            // 24600
#define OFF_PART (OFF_H + Hdim * Bdim)    // 32792
#define OFF_GX   (OFF_PART + 8 * 24 * 8)  // 34328
#define OFF_GH   (OFF_GX + 192)           // 34520
#define OFF_BHH  (OFF_GH + 192)           // 34712
#define SMEM_FLOATS (OFF_BHH + 24)        // 34736
#define SMEM_BYTES  (SMEM_FLOATS * 4)     // 138944

__global__ void __launch_bounds__(256, 1)
gru_rec_kernel(const float* __restrict__ W_hh, const float* __restrict__ b_hh,
               float* __restrict__ out)
{
    extern __shared__ float sm[];
    float* w_sh   = sm + OFF_W;
    float* h_sh   = sm + OFF_H;
    float* part   = sm + OFF_PART;
    float* gx_sh  = sm + OFF_GX;
    float* gh_sh  = sm + OFF_GH;
    float* bhh_sh = sm + OFF_BHH;
    __shared__ unsigned s_base;

    const int tid  = threadIdx.x;
    const int c    = blockIdx.x;
    const int warp = tid >> 5;
    const int lane = tid & 31;

    // ---- one-time: base from OWN flag (owner-only write -> race-free).
    // All flags and the epoch advance by exactly Tdim per launch, and the
    // previous launch fully finished (same stream) -> all equal at entry.
    if (tid == 0) {
        unsigned v;
        asm volatile("ld.volatile.global.u32 %0, [%1];"
                     : "=r"(v) : "l"(&g_flags[c * 64]) : "memory");
        s_base = v;
    }

    // ---- one-time: stage W_hh rows (pitch 1025 -> conflict-free row reads)
    for (int r = 0; r < 24; r++) {
        int g = (r >> 3) * Hdim + c * 8 + (r & 7);
        int k = tid * 4;
        float4 v = *(const float4*)&W_hh[(size_t)g * Hdim + k];
        float* dst = &w_sh[r * WPITCH + k];
        dst[0] = v.x; dst[1] = v.y; dst[2] = v.z; dst[3] = v.w;
    }
    if (tid < 24)
        bhh_sh[tid] = b_hh[(tid >> 3) * Hdim + c * 8 + (tid & 7)];
    __syncthreads();

    const unsigned base = s_base;

    for (int s = 0; s < Tdim; s++) {
        // ---- stage h_{s-1} into SMEM (layout [unit][b], straight copy)
        if (s == 0) {
            #pragma unroll
            for (int q = 0; q < 8; q++)
                *(float4*)&h_sh[(tid + q * 256) * 4] = make_float4(0.f, 0.f, 0.f, 0.f);
        } else {
            const float4* src = (const float4*)g_hbuf[(s - 1) & 1];
            #pragma unroll
            for (int q = 0; q < 8; q++)
                *(float4*)&h_sh[(tid + q * 256) * 4] = __ldcg(&src[tid + q * 256]);
        }

        // ---- prefetch this step's x-projection values
        float gxr = 0.f;
        int rr_ = tid % 24, bb_ = tid / 24;
        if (tid < 192) {
            int g = (rr_ >> 3) * Hdim + c * 8 + (rr_ & 7);
            gxr = g_xproj[((size_t)bb_ * Tdim + s) * G3 + g];
        }
        __syncthreads();

        // ---- recurrent GEMM slice: g_h partials
        if (lane < 24) {
            const float* wr = &w_sh[lane * WPITCH + warp * 128];
            const float* hb = &h_sh[warp * 128 * 8];
            ull a0 = 0, a1 = 0, a2 = 0, a3 = 0;
            #pragma unroll 16
            for (int k = 0; k < 128; k++) {
                ulonglong2 h01 = *(const ulonglong2*)&hb[k * 8];
                ulonglong2 h23 = *(const ulonglong2*)&hb[k * 8 + 4];
                float w = wr[k];
                ull w2 = pack2(w, w);
                a0 = ffma2(w2, h01.x, a0);
                a1 = ffma2(w2, h01.y, a1);
                a2 = ffma2(w2, h23.x, a2);
                a3 = ffma2(w2, h23.y, a3);
            }
            float* p = &part[(warp * 24 + lane) * 8];
            ulonglong2 s0; s0.x = a0; s0.y = a1;
            ulonglong2 s1; s1.x = a2; s1.y = a3;
            ((ulonglong2*)p)[0] = s0;
            ((ulonglong2*)p)[1] = s1;
        }
        __syncthreads();

        // ---- cross-warp reduction + bias
        if (tid < 192) {
            float sum = bhh_sh[rr_];
            #pragma unroll
            for (int w = 0; w < 8; w++)
                sum += part[(w * 24 + rr_) * 8 + bb_];
            gh_sh[rr_ * 8 + bb_] = sum;
            gx_sh[rr_ * 8 + bb_] = gxr;
        }
        __syncthreads();

        // ---- gate math + state update
        if (tid < 64) {
            int j = tid >> 3, b = tid & 7;
            float xr = gx_sh[j * 8 + b],        hr = gh_sh[j * 8 + b];
            float xz = gx_sh[(8 + j) * 8 + b],  hz = gh_sh[(8 + j) * 8 + b];
            float xn = gx_sh[(16 + j) * 8 + b], hn = gh_sh[(16 + j) * 8 + b];
            float rg = 1.f / (1.f + __expf(-(xr + hr)));
            float zg = 1.f / (1.f + __expf(-(xz + hz)));
            float ng = tanhf(xn + rg * hn);
            float hp = h_sh[(c * 8 + j) * 8 + b];
            float hv = (1.f - zg) * ng + zg * hp;
            g_hbuf[s & 1][(c * 8 + j) * 8 + b] = hv;
            out[((size_t)b * Tdim + s) * Hdim + c * 8 + j] = hv;
            __threadfence();
        }

        // ================= two-hop broadcast barrier =================
        const unsigned tgt = base + (unsigned)(s + 1);
        __syncthreads();                      // h stores happen-before release
        if (tid == 0)
            asm volatile("st.release.gpu.global.u32 [%0], %1;"
                         :: "l"(&g_flags[c * 64]), "r"(tgt) : "memory");
        if (c == 0 && warp == 0) {
            // aggregate: poll all 128 flags (acquire), then publish epoch
            bool ok;
            do {
                ok = true;
                #pragma unroll
                for (int q = 0; q < 4; q++) {
                    unsigned v;
                    asm volatile("ld.acquire.gpu.global.u32 %0, [%1];"
                                 : "=r"(v)
                                 : "l"(&g_flags[(lane + 32 * q) * 64])
                                 : "memory");
                    ok &= ((int)(v - tgt) >= 0);
                }
            } while (!__all_sync(0xffffffffu, ok));
            if (lane == 0)
                asm volatile("st.release.gpu.global.u32 [%0], %1;"
                             :: "l"(&g_epoch[0]), "r"(tgt) : "memory");
        }
        if (tid == 0) {
            // wait: poll the single broadcast epoch line
            unsigned v;
            do {
                asm volatile("ld.acquire.gpu.global.u32 %0, [%1];"
                             : "=r"(v) : "l"(&g_epoch[0]) : "memory");
            } while ((int)(v - tgt) < 0);
        }
        __syncthreads();                      // relay the release to the CTA
    }
}

// ============================================================================
extern "C" void kernel_launch(void* const* d_in, const int* in_sizes, int n_in,
                              void* d_out, int out_size)
{
    const float* x    = (const float*)d_in[0];
    const float* W_ih = (const float*)d_in[1];
    const float* b_ih = (const float*)d_in[2];
    const float* W_hh = (const float*)d_in[3];
    const float* b_hh = (const float*)d_in[4];
    float* out = (float*)d_out;
    (void)in_sizes; (void)n_in; (void)out_size;

    cudaFuncSetAttribute(gru_rec_kernel,
                         cudaFuncAttributeMaxDynamicSharedMemorySize, SMEM_BYTES);

    xproj_kernel<<<dim3(G3 / 128, (Bdim * Tdim) / 128), 256>>>(x, W_ih, b_ih);
    gru_rec_kernel<<<NCTA, 256, SMEM_BYTES>>>(W_hh, b_hh, out);
}

// round 14
// speedup vs baseline: 1.4029x; 1.4029x over previous
#include <cuda_runtime.h>
#include <cuda_bf16.h>
#include <cstdint>
#include <cstddef>

#define Hdim 1024
#define Bdim 8
#define Tdim 2048
#define G3   3072
#define NCTA 128

typedef unsigned long long ull;

// ---------------- device-global scratch (no runtime allocation) -------------
__device__ __align__(256) float g_xproj[(size_t)Bdim * Tdim * G3];   // [b][t][3H]
__device__ __align__(256) float g_hbuf[2][Hdim * Bdim];              // [unit][b]
__device__ __align__(256) ull   g_ctr;                               // monotonic

// ---------------- packed fp32x2 helpers ------------------------------------
__device__ __forceinline__ ull ffma2(ull a, ull b, ull c) {
    ull d;
    asm("fma.rn.f32x2 %0, %1, %2, %3;" : "=l"(d) : "l"(a), "l"(b), "l"(c));
    return d;
}
__device__ __forceinline__ ull pack2(float x, float y) {
    ull d; asm("mov.b64 %0, {%1, %2};" : "=l"(d) : "f"(x), "f"(y)); return d;
}
__device__ __forceinline__ void unpack2(ull d, float& x, float& y) {
    asm("mov.b64 {%0, %1}, %2;" : "=f"(x), "=f"(y) : "l"(d));
}

// ============================================================================
// Phase 1 (verbatim R2): x_proj = x @ W_ih^T + b_ih. 128x128 tile, BK=16.
// ============================================================================
#define PA 132

__global__ void __launch_bounds__(256)
xproj_kernel(const float* __restrict__ A, const float* __restrict__ W,
             const float* __restrict__ bias)
{
    __shared__ float As[16][PA];
    __shared__ float Bs[16][PA];

    const int tid = threadIdx.x;
    const int tx  = tid & 15;
    const int ty  = tid >> 4;
    const int m0  = blockIdx.y * 128;
    const int n0  = blockIdx.x * 128;

    const float* Abase = &A[(size_t)m0 * Hdim];
    const float* Wbase = &W[(size_t)n0 * Hdim];

    ull acc[8][4];
    #pragma unroll
    for (int i = 0; i < 8; i++)
        #pragma unroll
        for (int j = 0; j < 4; j++) acc[i][j] = 0ULL;

    for (int kt = 0; kt < Hdim / 16; kt++) {
        const int k0 = kt * 16;
        #pragma unroll
        for (int L = 0; L < 2; L++) {
            int id = tid + L * 256;
            int m  = id >> 2;
            int k4 = (id & 3) << 2;
            float4 va = *(const float4*)&Abase[(size_t)m * Hdim + k0 + k4];
            As[k4 + 0][m] = va.x; As[k4 + 1][m] = va.y;
            As[k4 + 2][m] = va.z; As[k4 + 3][m] = va.w;
            float4 vb = *(const float4*)&Wbase[(size_t)m * Hdim + k0 + k4];
            Bs[k4 + 0][m] = vb.x; Bs[k4 + 1][m] = vb.y;
            Bs[k4 + 2][m] = vb.z; Bs[k4 + 3][m] = vb.w;
        }
        __syncthreads();

        #pragma unroll
        for (int kk = 0; kk < 16; kk++) {
            float4 a0 = *(const float4*)&As[kk][ty * 8];
            float4 a1 = *(const float4*)&As[kk][ty * 8 + 4];
            ull a2[8] = { pack2(a0.x, a0.x), pack2(a0.y, a0.y),
                          pack2(a0.z, a0.z), pack2(a0.w, a0.w),
                          pack2(a1.x, a1.x), pack2(a1.y, a1.y),
                          pack2(a1.z, a1.z), pack2(a1.w, a1.w) };
            ulonglong2 b01 = *(const ulonglong2*)&Bs[kk][tx * 8];
            ulonglong2 b23 = *(const ulonglong2*)&Bs[kk][tx * 8 + 4];
            ull bp[4] = { b01.x, b01.y, b23.x, b23.y };
            #pragma unroll
            for (int i = 0; i < 8; i++)
                #pragma unroll
                for (int j = 0; j < 4; j++)
                    acc[i][j] = ffma2(a2[i], bp[j], acc[i][j]);
        }
        __syncthreads();
    }

    float bb[8];
    #pragma unroll
    for (int j = 0; j < 8; j++) bb[j] = bias[n0 + tx * 8 + j];

    #pragma unroll
    for (int i = 0; i < 8; i++) {
        size_t row = (size_t)(m0 + ty * 8 + i);
        float* crow = &g_xproj[row * G3 + n0 + tx * 8];
        #pragma unroll
        for (int j = 0; j < 4; j++) {
            float lo, hi; unpack2(acc[i][j], lo, hi);
            float2 v; v.x = lo + bb[2 * j]; v.y = hi + bb[2 * j + 1];
            *(float2*)(crow + 2 * j) = v;
        }
    }
}

// ============================================================================
// Phase 2: R2 pipeline + R2 barrier (measured best), with three surgical
// serial-path removals:
//  (1) no per-gate-thread __threadfence (grid barrier's sync+tid0 fence covers it)
//  (2) barrier split into arrive / overlap / wait: out stores + next-step gx
//      prefetch execute while tid0 polls
//  (3) everything else identical to R2
// ============================================================================
#define WPITCH 1025
#define OFF_W    0
#define OFF_H    (24 * WPITCH)            // 24600
#define OFF_PART (OFF_H + Hdim * Bdim)    // 32792
#define OFF_GX   (OFF_PART + 8 * 24 * 8)  // 34328
#define OFF_GH   (OFF_GX + 192)           // 34520
#define OFF_BHH  (OFF_GH + 192)           // 34712
#define SMEM_FLOATS (OFF_BHH + 24)        // 34736
#define SMEM_BYTES  (SMEM_FLOATS * 4)     // 138944

__global__ void __launch_bounds__(256, 1)
gru_rec_kernel(const float* __restrict__ W_hh, const float* __restrict__ b_hh,
               float* __restrict__ out)
{
    extern __shared__ float sm[];
    float* w_sh   = sm + OFF_W;
    float* h_sh   = sm + OFF_H;
    float* part   = sm + OFF_PART;
    float* gx_sh  = sm + OFF_GX;
    float* gh_sh  = sm + OFF_GH;
    float* bhh_sh = sm + OFF_BHH;

    const int tid  = threadIdx.x;
    const int c    = blockIdx.x;
    const int warp = tid >> 5;
    const int lane = tid & 31;

    // ---- one-time: stage W_hh rows (pitch 1025 -> conflict-free row reads)
    for (int r = 0; r < 24; r++) {
        int g = (r >> 3) * Hdim + c * 8 + (r & 7);
        int k = tid * 4;
        float4 v = *(const float4*)&W_hh[(size_t)g * Hdim + k];
        float* dst = &w_sh[r * WPITCH + k];
        dst[0] = v.x; dst[1] = v.y; dst[2] = v.z; dst[3] = v.w;
    }
    if (tid < 24)
        bhh_sh[tid] = b_hh[(tid >> 3) * Hdim + c * 8 + (tid & 7)];
    __syncthreads();

    const int rr_ = tid % 24, bb_ = tid / 24;   // prefetch/reduce mapping
    const int gg_ = (rr_ >> 3) * Hdim + c * 8 + (rr_ & 7);

    // ---- prefetch gx for step 0 (no dependency)
    float gxr = 0.f;
    if (tid < 192)
        gxr = g_xproj[((size_t)bb_ * Tdim + 0) * G3 + gg_];

    for (int s = 0; s < Tdim; s++) {
        // ---- stage h_{s-1} into SMEM (layout [unit][b], straight copy)
        if (s == 0) {
            #pragma unroll
            for (int q = 0; q < 8; q++)
                *(float4*)&h_sh[(tid + q * 256) * 4] = make_float4(0.f, 0.f, 0.f, 0.f);
        } else {
            const float4* src = (const float4*)g_hbuf[(s - 1) & 1];
            #pragma unroll
            for (int q = 0; q < 8; q++)
                *(float4*)&h_sh[(tid + q * 256) * 4] = __ldcg(&src[tid + q * 256]);
        }
        __syncthreads();

        // ---- recurrent GEMM slice: g_h partials
        if (lane < 24) {
            const float* wr = &w_sh[lane * WPITCH + warp * 128];
            const float* hb = &h_sh[warp * 128 * 8];
            ull a0 = 0, a1 = 0, a2 = 0, a3 = 0;
            #pragma unroll 16
            for (int k = 0; k < 128; k++) {
                ulonglong2 h01 = *(const ulonglong2*)&hb[k * 8];      // bcast
                ulonglong2 h23 = *(const ulonglong2*)&hb[k * 8 + 4];  // bcast
                float w = wr[k];
                ull w2 = pack2(w, w);
                a0 = ffma2(w2, h01.x, a0);
                a1 = ffma2(w2, h01.y, a1);
                a2 = ffma2(w2, h23.x, a2);
                a3 = ffma2(w2, h23.y, a3);
            }
            float* p = &part[(warp * 24 + lane) * 8];
            ulonglong2 s0; s0.x = a0; s0.y = a1;
            ulonglong2 s1; s1.x = a2; s1.y = a3;
            ((ulonglong2*)p)[0] = s0;
            ((ulonglong2*)p)[1] = s1;
        }
        __syncthreads();

        // ---- cross-warp reduction + bias (gx from held register)
        if (tid < 192) {
            float sum = bhh_sh[rr_];
            #pragma unroll
            for (int w = 0; w < 8; w++)
                sum += part[(w * 24 + rr_) * 8 + bb_];
            gh_sh[rr_ * 8 + bb_] = sum;
            gx_sh[rr_ * 8 + bb_] = gxr;
        }
        __syncthreads();

        // ---- gate math + h publish (NO fence, NO out store here)
        float hv = 0.f;
        int j = tid >> 3, b = tid & 7;
        if (tid < 64) {
            float xr = gx_sh[j * 8 + b],        hr = gh_sh[j * 8 + b];
            float xz = gx_sh[(8 + j) * 8 + b],  hz = gh_sh[(8 + j) * 8 + b];
            float xn = gx_sh[(16 + j) * 8 + b], hn = gh_sh[(16 + j) * 8 + b];
            float rg = 1.f / (1.f + __expf(-(xr + hr)));
            float zg = 1.f / (1.f + __expf(-(xz + hz)));
            float ng = tanhf(xn + rg * hn);
            float hp = h_sh[(c * 8 + j) * 8 + b];
            hv = (1.f - zg) * ng + zg * hp;
            g_hbuf[s & 1][(c * 8 + j) * 8 + b] = hv;
        }

        // ================= grid barrier: arrive / overlap / wait ============
        __syncthreads();                       // h stores happen-before release
        ull tgt = 0;
        if (tid == 0) {
            __threadfence();                   // publish h GPU-wide
            ull my = atomicAdd(&g_ctr, 1ULL) + 1ULL;   // arrive (release-ish per R2)
            tgt = ((my + NCTA - 1) / NCTA) * NCTA;
        }

        // overlap work while tid0's arrival propagates / others arrive:
        if (tid < 64)                          // out store (not cross-CTA data)
            out[((size_t)b * Tdim + s) * Hdim + c * 8 + j] = hv;
        if (tid < 192) {                       // prefetch gx for step s+1
            int sn = (s + 1 < Tdim) ? s + 1 : s;
            gxr = g_xproj[((size_t)bb_ * Tdim + sn) * G3 + gg_];
        }

        if (tid == 0) {                        // wait: poll the single line
            ull v;
            do {
                asm volatile("ld.acquire.gpu.u64 %0, [%1];"
                             : "=l"(v) : "l"(&g_ctr) : "memory");
            } while (v < tgt);
        }
        __syncthreads();                       // relay release to the CTA
    }
}

// ============================================================================
extern "C" void kernel_launch(void* const* d_in, const int* in_sizes, int n_in,
                              void* d_out, int out_size)
{
    const float* x    = (const float*)d_in[0];
    const float* W_ih = (const float*)d_in[1];
    const float* b_ih = (const float*)d_in[2];
    const float* W_hh = (const float*)d_in[3];
    const float* b_hh = (const float*)d_in[4];
    float* out = (float*)d_out;
    (void)in_sizes; (void)n_in; (void)out_size;

    cudaFuncSetAttribute(gru_rec_kernel,
                         cudaFuncAttributeMaxDynamicSharedMemorySize, SMEM_BYTES);

    xproj_kernel<<<dim3(G3 / 128, (Bdim * Tdim) / 128), 256>>>(x, W_ih, b_ih);
    gru_rec_kernel<<<NCTA, 256, SMEM_BYTES>>>(W_hh, b_hh, out);
}

// round 15
// speedup vs baseline: 1.4360x; 1.0236x over previous
#include <cuda_runtime.h>
#include <cuda_bf16.h>
#include <cstdint>
#include <cstddef>

#define Hdim 1024
#define Bdim 8
#define Tdim 2048
#define G3   3072
#define NCTA 128

typedef unsigned long long ull;

// ---------------- device-global scratch (no runtime allocation) -------------
__device__ __align__(256) float g_xproj[(size_t)Bdim * Tdim * G3];   // [b][t][3H]
__device__ __align__(256) float g_hbuf[2][Hdim * Bdim];              // [unit][b]
__device__ __align__(256) ull   g_ctr;                               // monotonic

// ---------------- packed fp32x2 helpers ------------------------------------
__device__ __forceinline__ ull ffma2(ull a, ull b, ull c) {
    ull d;
    asm("fma.rn.f32x2 %0, %1, %2, %3;" : "=l"(d) : "l"(a), "l"(b), "l"(c));
    return d;
}
__device__ __forceinline__ ull pack2(float x, float y) {
    ull d; asm("mov.b64 %0, {%1, %2};" : "=l"(d) : "f"(x), "f"(y)); return d;
}
__device__ __forceinline__ void unpack2(ull d, float& x, float& y) {
    asm("mov.b64 {%0, %1}, %2;" : "=f"(x), "=f"(y) : "l"(d));
}

// ============================================================================
// Phase 1 (verbatim R2): x_proj = x @ W_ih^T + b_ih. 128x128 tile, BK=16.
// ============================================================================
#define PA 132

__global__ void __launch_bounds__(256)
xproj_kernel(const float* __restrict__ A, const float* __restrict__ W,
             const float* __restrict__ bias)
{
    __shared__ float As[16][PA];
    __shared__ float Bs[16][PA];

    const int tid = threadIdx.x;
    const int tx  = tid & 15;
    const int ty  = tid >> 4;
    const int m0  = blockIdx.y * 128;
    const int n0  = blockIdx.x * 128;

    const float* Abase = &A[(size_t)m0 * Hdim];
    const float* Wbase = &W[(size_t)n0 * Hdim];

    ull acc[8][4];
    #pragma unroll
    for (int i = 0; i < 8; i++)
        #pragma unroll
        for (int j = 0; j < 4; j++) acc[i][j] = 0ULL;

    for (int kt = 0; kt < Hdim / 16; kt++) {
        const int k0 = kt * 16;
        #pragma unroll
        for (int L = 0; L < 2; L++) {
            int id = tid + L * 256;
            int m  = id >> 2;
            int k4 = (id & 3) << 2;
            float4 va = *(const float4*)&Abase[(size_t)m * Hdim + k0 + k4];
            As[k4 + 0][m] = va.x; As[k4 + 1][m] = va.y;
            As[k4 + 2][m] = va.z; As[k4 + 3][m] = va.w;
            float4 vb = *(const float4*)&Wbase[(size_t)m * Hdim + k0 + k4];
            Bs[k4 + 0][m] = vb.x; Bs[k4 + 1][m] = vb.y;
            Bs[k4 + 2][m] = vb.z; Bs[k4 + 3][m] = vb.w;
        }
        __syncthreads();

        #pragma unroll
        for (int kk = 0; kk < 16; kk++) {
            float4 a0 = *(const float4*)&As[kk][ty * 8];
            float4 a1 = *(const float4*)&As[kk][ty * 8 + 4];
            ull a2[8] = { pack2(a0.x, a0.x), pack2(a0.y, a0.y),
                          pack2(a0.z, a0.z), pack2(a0.w, a0.w),
                          pack2(a1.x, a1.x), pack2(a1.y, a1.y),
                          pack2(a1.z, a1.z), pack2(a1.w, a1.w) };
            ulonglong2 b01 = *(const ulonglong2*)&Bs[kk][tx * 8];
            ulonglong2 b23 = *(const ulonglong2*)&Bs[kk][tx * 8 + 4];
            ull bp[4] = { b01.x, b01.y, b23.x, b23.y };
            #pragma unroll
            for (int i = 0; i < 8; i++)
                #pragma unroll
                for (int j = 0; j < 4; j++)
                    acc[i][j] = ffma2(a2[i], bp[j], acc[i][j]);
        }
        __syncthreads();
    }

    float bb[8];
    #pragma unroll
    for (int j = 0; j < 8; j++) bb[j] = bias[n0 + tx * 8 + j];

    #pragma unroll
    for (int i = 0; i < 8; i++) {
        size_t row = (size_t)(m0 + ty * 8 + i);
        float* crow = &g_xproj[row * G3 + n0 + tx * 8];
        #pragma unroll
        for (int j = 0; j < 4; j++) {
            float lo, hi; unpack2(acc[i][j], lo, hi);
            float2 v; v.x = lo + bb[2 * j]; v.y = hi + bb[2 * j + 1];
            *(float2*)(crow + 2 * j) = v;
        }
    }
}

// ============================================================================
// Phase 2: R14 skeleton (== R2 within noise) with two LSU-pressure cuts:
//  (a) W_hh in SMEM as XOR-swizzled float4 rows: chunk c of row r stored at
//      c ^ (r & 7).  GEMM reads LDS.128 (4 k per instr), 3 balanced
//      wavefronts across the 24 active lanes.  w-LDS instr: 1024 -> 256 /step.
//  (b) part[] pitch 66 (2-way instead of 8-way conflicts on reduction reads);
//      written with 8-byte ull stores ONLY (264B rows are 8B- not 16B-aligned).
// Barrier/staging/gates identical to R14.
// ============================================================================
#define OFF_W    0                        // 24*1024 = 24576 floats (96 KB)
#define OFF_H    24576                    // 8192 floats
#define OFF_PART 32768                    // 24*66 = 1584
#define OFF_GX   34352                    // 192
#define OFF_GH   34544                    // 192
#define OFF_BHH  34736                    // 24
#define SMEM_FLOATS 34760
#define SMEM_BYTES  (SMEM_FLOATS * 4)     // 139040

__global__ void __launch_bounds__(256, 1)
gru_rec_kernel(const float* __restrict__ W_hh, const float* __restrict__ b_hh,
               float* __restrict__ out)
{
    extern __shared__ float sm[];
    float* w_sh   = sm + OFF_W;
    float* h_sh   = sm + OFF_H;
    float* part   = sm + OFF_PART;
    float* gx_sh  = sm + OFF_GX;
    float* gh_sh  = sm + OFF_GH;
    float* bhh_sh = sm + OFF_BHH;

    const int tid  = threadIdx.x;
    const int c    = blockIdx.x;
    const int warp = tid >> 5;
    const int lane = tid & 31;

    // ---- one-time: stage W_hh rows, XOR-swizzled float4 chunks
    for (int r = 0; r < 24; r++) {
        int g = (r >> 3) * Hdim + c * 8 + (r & 7);
        float4 v = *(const float4*)&W_hh[(size_t)g * Hdim + tid * 4];
        int cs = tid ^ (r & 7);                       // swizzled chunk index
        *(float4*)&w_sh[r * 1024 + cs * 4] = v;
    }
    if (tid < 24)
        bhh_sh[tid] = b_hh[(tid >> 3) * Hdim + c * 8 + (tid & 7)];
    __syncthreads();

    const int rr_ = tid % 24, bb_ = tid / 24;   // prefetch/reduce mapping
    const int gg_ = (rr_ >> 3) * Hdim + c * 8 + (rr_ & 7);

    // ---- prefetch gx for step 0
    float gxr = 0.f;
    if (tid < 192)
        gxr = g_xproj[((size_t)bb_ * Tdim + 0) * G3 + gg_];

    for (int s = 0; s < Tdim; s++) {
        // ---- stage h_{s-1} into SMEM (layout [unit][b], straight copy)
        if (s == 0) {
            #pragma unroll
            for (int q = 0; q < 8; q++)
                *(float4*)&h_sh[(tid + q * 256) * 4] = make_float4(0.f, 0.f, 0.f, 0.f);
        } else {
            const float4* src = (const float4*)g_hbuf[(s - 1) & 1];
            #pragma unroll
            for (int q = 0; q < 8; q++)
                *(float4*)&h_sh[(tid + q * 256) * 4] = __ldcg(&src[tid + q * 256]);
        }
        __syncthreads();

        // ---- recurrent GEMM slice: g_h partials (lane = gate row, 24 active)
        if (lane < 24) {
            const float* wrow = &w_sh[lane * 1024];
            const int    xr   = lane & 7;
            const float* hb   = &h_sh[warp * 1024];
            ull a0 = 0, a1 = 0, a2 = 0, a3 = 0;
            #pragma unroll 8
            for (int j = 0; j < 32; j++) {
                int cs = (warp * 32 + j) ^ xr;
                float4 wv = *(const float4*)&wrow[cs * 4];
                #pragma unroll
                for (int q = 0; q < 4; q++) {
                    int k = j * 4 + q;
                    ulonglong2 h01 = *(const ulonglong2*)&hb[k * 8];      // bcast
                    ulonglong2 h23 = *(const ulonglong2*)&hb[k * 8 + 4];  // bcast
                    float w = (q == 0) ? wv.x : (q == 1) ? wv.y
                            : (q == 2) ? wv.z : wv.w;
                    ull w2 = pack2(w, w);
                    a0 = ffma2(w2, h01.x, a0);
                    a1 = ffma2(w2, h01.y, a1);
                    a2 = ffma2(w2, h23.x, a2);
                    a3 = ffma2(w2, h23.y, a3);
                }
            }
            // pitch-66 rows: 8-byte stores only (264B rows not 16B-aligned)
            ull* p = (ull*)&part[lane * 66 + warp * 8];
            p[0] = a0; p[1] = a1; p[2] = a2; p[3] = a3;
        }
        __syncthreads();

        // ---- cross-warp reduction + bias (2-way conflicts with pitch 66)
        if (tid < 192) {
            float sum = bhh_sh[rr_];
            #pragma unroll
            for (int w = 0; w < 8; w++)
                sum += part[rr_ * 66 + w * 8 + bb_];
            gh_sh[rr_ * 8 + bb_] = sum;
            gx_sh[rr_ * 8 + bb_] = gxr;
        }
        __syncthreads();

        // ---- gate math + h publish
        float hv = 0.f;
        int j = tid >> 3, b = tid & 7;
        if (tid < 64) {
            float xr2 = gx_sh[j * 8 + b],        hr = gh_sh[j * 8 + b];
            float xz  = gx_sh[(8 + j) * 8 + b],  hz = gh_sh[(8 + j) * 8 + b];
            float xn  = gx_sh[(16 + j) * 8 + b], hn = gh_sh[(16 + j) * 8 + b];
            float rg = 1.f / (1.f + __expf(-(xr2 + hr)));
            float zg = 1.f / (1.f + __expf(-(xz + hz)));
            float ng = tanhf(xn + rg * hn);
            float hp = h_sh[(c * 8 + j) * 8 + b];
            hv = (1.f - zg) * ng + zg * hp;
            g_hbuf[s & 1][(c * 8 + j) * 8 + b] = hv;
        }

        // ================= grid barrier: arrive / overlap / wait ============
        __syncthreads();                       // h stores happen-before release
        ull tgt = 0;
        if (tid == 0) {
            __threadfence();                   // publish h GPU-wide
            ull my = atomicAdd(&g_ctr, 1ULL) + 1ULL;
            tgt = ((my + NCTA - 1) / NCTA) * NCTA;
        }

        // overlap work while arrivals propagate:
        if (tid < 64)
            out[((size_t)b * Tdim + s) * Hdim + c * 8 + j] = hv;
        if (tid < 192) {
            int sn = (s + 1 < Tdim) ? s + 1 : s;
            gxr = g_xproj[((size_t)bb_ * Tdim + sn) * G3 + gg_];
        }

        if (tid == 0) {
            ull v;
            do {
                asm volatile("ld.acquire.gpu.u64 %0, [%1];"
                             : "=l"(v) : "l"(&g_ctr) : "memory");
            } while (v < tgt);
        }
        __syncthreads();                       // relay release to the CTA
    }
}

// ============================================================================
extern "C" void kernel_launch(void* const* d_in, const int* in_sizes, int n_in,
                              void* d_out, int out_size)
{
    const float* x    = (const float*)d_in[0];
    const float* W_ih = (const float*)d_in[1];
    const float* b_ih = (const float*)d_in[2];
    const float* W_hh = (const float*)d_in[3];
    const float* b_hh = (const float*)d_in[4];
    float* out = (float*)d_out;
    (void)in_sizes; (void)n_in; (void)out_size;

    cudaFuncSetAttribute(gru_rec_kernel,
                         cudaFuncAttributeMaxDynamicSharedMemorySize, SMEM_BYTES);

    xproj_kernel<<<dim3(G3 / 128, (Bdim * Tdim) / 128), 256>>>(x, W_ih, b_ih);
    gru_rec_kernel<<<NCTA, 256, SMEM_BYTES>>>(W_hh, b_hh, out);
}